// round 16
// baseline (speedup 1.0000x reference)
#include <cuda_runtime.h>
#include <cuda_bf16.h>

// ODE-GRU: B=128, L=2048, I=D=64.
// Round 16: 3-phase M-trick with NO thread holding 3 rowsets (fixes R14/R15
// spills). 320 threads (reg cap 204):
//   gates  w0,w1  (64):  dw1+dw2 regs  -> t1 (A), f (B), gates (C)
//   workers w2-w7(192):  w_hh+M regs   -> G1 (A), G2 (B), idle (C)
//   gx     w8,w9  (64):  w_ih rows g,64+g in regs; rows 128+g in SMEM
//                        (transposed [k][g], conflict-free, self-owned)
//                        -> gx[t+1] row g (A), row 64+g (B),
//                           row 128+g from smem (C) + x/dt prefetch (C)
// gh = G1 + dt*G2, G2 = t1*M^T + c, M = w_hh@dw2, c = w_hh@db2 (validated).
// 3 bar.sync(0,320)/step. tanh.approx t1; precise gates.

#define NB 128
#define NL 2048
#define ND 64
#define NG 192
#define NT 320

typedef unsigned long long u64;

__device__ float g_M[NG * ND];
__device__ float g_c[NG];

#define BARRIER() asm volatile("bar.sync 0, %0;" :: "n"(NT) : "memory")

__device__ __forceinline__ u64 fma2(u64 a, u64 b, u64 c) {
    u64 d;
    asm("fma.rn.f32x2 %0, %1, %2, %3;" : "=l"(d) : "l"(a), "l"(b), "l"(c));
    return d;
}
__device__ __forceinline__ u64 add2(u64 a, u64 b) {
    u64 d;
    asm("add.rn.f32x2 %0, %1, %2;" : "=l"(d) : "l"(a), "l"(b));
    return d;
}
__device__ __forceinline__ u64 pk(float lo, float hi) {
    u64 r;
    asm("mov.b64 %0, {%1, %2};" : "=l"(r) : "f"(lo), "f"(hi));
    return r;
}

// dot(w_row[64], v[64]) + bias, w pre-packed f32x2 in registers.
__device__ __forceinline__ float dot64p(const u64* __restrict__ w,
                                        const float* __restrict__ v,
                                        float bias)
{
    const ulonglong2* __restrict__ v2 = (const ulonglong2*)v;
    u64 a0 = pk(bias, 0.f), a1 = 0ull, a2 = 0ull, a3 = 0ull;
#pragma unroll
    for (int q = 0; q < 8; q++) {
        ulonglong2 p = v2[2*q];
        ulonglong2 r = v2[2*q + 1];
        a0 = fma2(w[4*q+0], p.x, a0);
        a1 = fma2(w[4*q+1], p.y, a1);
        a2 = fma2(w[4*q+2], r.x, a2);
        a3 = fma2(w[4*q+3], r.y, a3);
    }
    u64 s = add2(add2(a0, a1), add2(a2, a3));
    return __uint_as_float((unsigned)s) + __uint_as_float((unsigned)(s >> 32));
}

// dot with weights in transposed smem ([k][g] float2 layout, column g).
__device__ __forceinline__ float dot64s(const float2* __restrict__ ws, int g,
                                        const float* __restrict__ v, float bias)
{
    const u64* __restrict__ v2 = (const u64*)v;
    u64 a0 = pk(bias, 0.f), a1 = 0ull, a2 = 0ull, a3 = 0ull;
#pragma unroll
    for (int q = 0; q < 8; q++) {
        a0 = fma2(*(const u64*)&ws[(4*q+0)*ND + g], v2[4*q+0], a0);
        a1 = fma2(*(const u64*)&ws[(4*q+1)*ND + g], v2[4*q+1], a1);
        a2 = fma2(*(const u64*)&ws[(4*q+2)*ND + g], v2[4*q+2], a2);
        a3 = fma2(*(const u64*)&ws[(4*q+3)*ND + g], v2[4*q+3], a3);
    }
    u64 s = add2(add2(a0, a1), add2(a2, a3));
    return __uint_as_float((unsigned)s) + __uint_as_float((unsigned)(s >> 32));
}

__device__ __forceinline__ float sigmoidf_(float a) {      // precise (gates)
    return __fdividef(1.f, 1.f + __expf(-a));
}
__device__ __forceinline__ float tanhf_fast(float x) {     // precise (n-gate)
    float e = __expf(2.f * x);
    return 1.f - __fdividef(2.f, e + 1.f);
}
__device__ __forceinline__ float tanh_ap(float x) {        // approx (t1 only)
    float y;
    asm("tanh.approx.f32 %0, %1;" : "=f"(y) : "f"(x));
    return y;
}

// ---------------- setup: M = w_hh @ dw2 (192x64), c = w_hh @ db2 -----------
__global__ __launch_bounds__(64)
void setup_Mc_kernel(const float* __restrict__ w_hh,
                     const float* __restrict__ dw2,
                     const float* __restrict__ db2)
{
    const int k = blockIdx.x;    // 0..191
    const int j = threadIdx.x;   // 0..63
    __shared__ float row[ND];
    row[j] = w_hh[k * ND + j];
    __syncthreads();
    float acc = 0.f;
#pragma unroll 8
    for (int i = 0; i < ND; i++) acc = fmaf(row[i], dw2[i * ND + j], acc);
    g_M[k * ND + j] = acc;
    if (j == 0) {
        float c = 0.f;
        for (int i = 0; i < ND; i++) c = fmaf(row[i], db2[i], c);
        g_c[k] = c;
    }
}

// ---------------- recurrent kernel -----------------------------------------
__global__ __launch_bounds__(NT, 1)
void odegru_kernel(const float* __restrict__ x,
                   const float* __restrict__ tdel,
                   const int*   __restrict__ seq,
                   const float* __restrict__ h0,
                   const float* __restrict__ w_ih,
                   const float* __restrict__ w_hh,
                   const float* __restrict__ b_ih,
                   const float* __restrict__ b_hh,
                   const float* __restrict__ dw1,
                   const float* __restrict__ db1,
                   const float* __restrict__ dw2,
                   const float* __restrict__ db2,
                   float* __restrict__ out)
{
    const int b   = blockIdx.x;
    const int tid = threadIdx.x;

    __shared__ __align__(16) float sh_h[ND];
    __shared__ __align__(16) float sh_t1[ND];
    __shared__ __align__(16) float sh_G1[NG];     // h*w_hh^T + b_hh
    __shared__ __align__(16) float sh_G2[NG];     // t1*M^T + c
    __shared__ __align__(16) float sh_gx[2][NG];  // double-buffered by parity
    __shared__ __align__(16) float sh_x[2][ND];   // x[t] in buffer t&1
    __shared__ float sh_dt[2];
    __shared__ __align__(16) float2 sh_w3[32 * ND]; // w_ih rows 128..191, [k][g]

    const int sl = seq[b];

    if (tid < 64) {
        // ================= GATE WARPS (w0,w1) =================
        const int j = tid;
        u64 wA[32], wB[32];                       // dw1 row j, dw2 row j
        {
            const u64* pA = (const u64*)(dw1 + j * ND);
            const u64* pB = (const u64*)(dw2 + j * ND);
#pragma unroll
            for (int k = 0; k < 32; k++) { wA[k] = pA[k]; wB[k] = pB[k]; }
        }
        const float bA = db1[j], bB = db2[j];
        float* outb = out + (size_t)b * NL * ND;

        float hreg = h0[j];
        sh_h[j] = hreg;
        float fin = 0.f;
        BARRIER();                                // pre1
        BARRIER();                                // pre2: gx[0] ready

        for (int t = 0; t < NL; t++) {
            const int cur = t & 1;
            // A: preload gx/dt (stable this phase); t1 dot
            float gx0 = sh_gx[cur][j];
            float gx1 = sh_gx[cur][64 + j];
            float gx2 = sh_gx[cur][128 + j];
            float dt  = sh_dt[cur];
            sh_t1[j] = tanh_ap(dot64p(wA, sh_h, bA));
            BARRIER();                            // syncA

            // B: f in register; preload G1 (final since syncA)
            float f    = dot64p(wB, sh_t1, bB);
            float G1_0 = sh_G1[j];
            float G1_1 = sh_G1[64 + j];
            float G1_2 = sh_G1[128 + j];
            BARRIER();                            // syncB

            // C: gates (h and f never touch smem); gh = G1 + dt*G2
            float ho = fmaf(dt, f, hreg);
            float g0 = fmaf(dt, sh_G2[j],       G1_0);
            float g1 = fmaf(dt, sh_G2[64 + j],  G1_1);
            float g2 = fmaf(dt, sh_G2[128 + j], G1_2);
            float r  = sigmoidf_(gx0 + g0);
            float z  = sigmoidf_(gx1 + g1);
            float n  = tanhf_fast(fmaf(r, g2, gx2));
            float hn = fmaf(z, ho - n, n);        // (1-z)*n + z*ho
            hreg = hn;
            sh_h[j] = hn;
            outb[(size_t)t * ND + j] = hn;
            if (t == sl - 1) fin = hn;
            BARRIER();                            // syncC
        }
        out[(size_t)NB * NL * ND + (size_t)b * ND + j] = fin;
    } else if (tid < 256) {
        // ================= WORKER WARPS (w2-w7) =================
        const int k2 = tid - 64;                  // 0..191
        u64 wA[32], wB[32];                       // w_hh row k2, M row k2
        {
            const u64* pA = (const u64*)(w_hh + k2 * ND);
            const u64* pB = (const u64*)(g_M + k2 * ND);
#pragma unroll
            for (int k = 0; k < 32; k++) { wA[k] = pA[k]; wB[k] = pB[k]; }
        }
        const float bA = b_hh[k2], bB = g_c[k2];
        BARRIER();                                // pre1
        BARRIER();                                // pre2

        for (int t = 0; t < NL; t++) {
            sh_G1[k2] = dot64p(wA, sh_h, bA);     // A
            BARRIER();                            // syncA
            sh_G2[k2] = dot64p(wB, sh_t1, bB);    // B
            BARRIER();                            // syncB
            BARRIER();                            // syncC (idle in C)
        }
    } else {
        // ================= GX WARPS (w8,w9) =================
        const int g = tid - 256;                  // 0..63
        u64 wP[32], wQ[32];                       // w_ih rows g, 64+g
        {
            const u64* pP = (const u64*)(w_ih + g * ND);
            const u64* pQ = (const u64*)(w_ih + (64 + g) * ND);
#pragma unroll
            for (int k = 0; k < 32; k++) { wP[k] = pP[k]; wQ[k] = pQ[k]; }
        }
        const float bP = b_ih[g], bQ = b_ih[64 + g], bR = b_ih[128 + g];

        // w_ih row 128+g -> transposed smem column g (self-owned)
        {
            const float2* src = (const float2*)(w_ih + (128 + g) * ND);
#pragma unroll
            for (int k = 0; k < 32; k++) sh_w3[k * ND + g] = src[k];
        }

        const float* xb  = x + (size_t)b * NL * ND;
        const float* dtb = tdel + (size_t)b * NL;

        // x/dt init + prefetch (thread g owns element g)
        sh_x[0][g] = xb[g];                          // t=0 live (sl >= 1)
        sh_x[1][g] = (1 < sl) ? xb[ND + g] : 0.f;    // x[1] masked
        float xA = xb[2 * ND + g];                   // x[2] (masked at commit)
        float dtA = 0.f;
        if (g == 0) {
            sh_dt[0] = dtb[0];
            sh_dt[1] = (1 < sl) ? dtb[1] : 0.f;
            dtA = dtb[2];
        }
        BARRIER();                                // pre1: x/dt visible
        // prologue: gx[0] (all 3 rows) from sh_x[0]
        sh_gx[0][g]       = dot64p(wP, sh_x[0], bP);
        sh_gx[0][64 + g]  = dot64p(wQ, sh_x[0], bQ);
        sh_gx[0][128 + g] = dot64s(sh_w3, g, sh_x[0], bR);
        BARRIER();                                // pre2: gx[0] ready

        for (int t = 0; t < NL; t++) {
            const int cur = t & 1, nxt = cur ^ 1;
            // A: gx[t+1] row g  (x[t+1] lives in sh_x[nxt])
            if (t + 1 < NL)
                sh_gx[nxt][g] = dot64p(wP, sh_x[nxt], bP);
            BARRIER();                            // syncA
            // B: gx[t+1] row 64+g
            if (t + 1 < NL)
                sh_gx[nxt][64 + g] = dot64p(wQ, sh_x[nxt], bQ);
            BARRIER();                            // syncB
            // C: gx[t+1] row 128+g (smem weights); commit x/dt[t+2]; LDG t+3
            if (t + 1 < NL)
                sh_gx[nxt][128 + g] = dot64s(sh_w3, g, sh_x[nxt], bR);
            sh_x[cur][g] = (t + 2 < sl) ? xA : 0.f;   // PaddedBatch mask
            if (g == 0) sh_dt[cur] = (t + 2 < sl) ? dtA : 0.f;
            if (t + 3 < NL) {
                xA = xb[(size_t)(t + 3) * ND + g];
                if (g == 0) dtA = dtb[t + 3];
            }
            BARRIER();                            // syncC
        }
    }
}

extern "C" void kernel_launch(void* const* d_in, const int* in_sizes, int n_in,
                              void* d_out, int out_size)
{
    const float* x    = (const float*)d_in[0];
    const float* tdel = (const float*)d_in[1];
    const int*   seq  = (const int*)  d_in[2];
    const float* h0   = (const float*)d_in[3];
    const float* w_ih = (const float*)d_in[4];
    const float* w_hh = (const float*)d_in[5];
    const float* b_ih = (const float*)d_in[6];
    const float* b_hh = (const float*)d_in[7];
    const float* dw1  = (const float*)d_in[8];
    const float* db1  = (const float*)d_in[9];
    const float* dw2  = (const float*)d_in[10];
    const float* db2  = (const float*)d_in[11];

    setup_Mc_kernel<<<NG, 64>>>(w_hh, dw2, db2);
    odegru_kernel<<<NB, NT>>>(x, tdel, seq, h0, w_ih, w_hh, b_ih, b_hh,
                              dw1, db1, dw2, db2, (float*)d_out);
}

// round 17
// speedup vs baseline: 2.0793x; 2.0793x over previous
#include <cuda_runtime.h>
#include <cuda_bf16.h>

// ODE-GRU: B=128, L=2048, I=D=64.
// Round 17: 3-phase recurrence that FITS registers (704-row demand of the
// in-CTA 3-phase proven impossible in R14-16; removing w_ih leaves exactly
// 512 rows = capacity). gx = x*w_ih^T+b_ih precomputed by a batch GEMM into
// 201MB scratch; gate warps prefetch their 3 floats/step with ~5-phase LDG
// cover. Recurrent (256 thr, 3 bar/step):
//   A: t1 (gates w6,w7)          || G1 = h*w_hh^T+b_hh (workers w0-5)
//   B: f reg + G1 preload (gates)|| G2 = t1*M^T+c      (workers)
//   C: gates (gh = G1 + dt*G2)   || workers idle
// Gates on the HIGHEST warp ids (hi-wid-first arbiter -> serial chain gets
// issue priority). tanh.approx t1 (validated); precise gates.

#define NB 128
#define NL 2048
#define ND 64
#define NG 192
#define GXR 64   // timesteps per gx-GEMM block

typedef unsigned long long u64;

__device__ float g_M[NG * ND];
__device__ float g_c[NG];
__device__ float g_gx[(size_t)NB * NL * NG];   // 201 MB scratch

#define BARRIER() asm volatile("bar.sync 0, 256;" ::: "memory")

__device__ __forceinline__ u64 fma2(u64 a, u64 b, u64 c) {
    u64 d;
    asm("fma.rn.f32x2 %0, %1, %2, %3;" : "=l"(d) : "l"(a), "l"(b), "l"(c));
    return d;
}
__device__ __forceinline__ u64 add2(u64 a, u64 b) {
    u64 d;
    asm("add.rn.f32x2 %0, %1, %2;" : "=l"(d) : "l"(a), "l"(b));
    return d;
}
__device__ __forceinline__ u64 pk(float lo, float hi) {
    u64 r;
    asm("mov.b64 %0, {%1, %2};" : "=l"(r) : "f"(lo), "f"(hi));
    return r;
}

// dot(w_row[64], v[64]) + bias, w pre-packed f32x2 (bias seeded in acc).
__device__ __forceinline__ float dot64p(const u64* __restrict__ w,
                                        const float* __restrict__ v,
                                        float bias)
{
    const ulonglong2* __restrict__ v2 = (const ulonglong2*)v;
    u64 a0 = pk(bias, 0.f), a1 = 0ull, a2 = 0ull, a3 = 0ull;
#pragma unroll
    for (int q = 0; q < 8; q++) {
        ulonglong2 p = v2[2*q];
        ulonglong2 r = v2[2*q + 1];
        a0 = fma2(w[4*q+0], p.x, a0);
        a1 = fma2(w[4*q+1], p.y, a1);
        a2 = fma2(w[4*q+2], r.x, a2);
        a3 = fma2(w[4*q+3], r.y, a3);
    }
    u64 s = add2(add2(a0, a1), add2(a2, a3));
    return __uint_as_float((unsigned)s) + __uint_as_float((unsigned)(s >> 32));
}

__device__ __forceinline__ float sigmoidf_(float a) {      // precise (gates)
    return __fdividef(1.f, 1.f + __expf(-a));
}
__device__ __forceinline__ float tanhf_fast(float x) {     // precise (n-gate)
    float e = __expf(2.f * x);
    return 1.f - __fdividef(2.f, e + 1.f);
}
__device__ __forceinline__ float tanh_ap(float x) {        // approx (t1 only)
    float y;
    asm("tanh.approx.f32 %0, %1;" : "=f"(y) : "f"(x));
    return y;
}

// ---------------- setup: M = w_hh @ dw2 (192x64), c = w_hh @ db2 -----------
__global__ __launch_bounds__(64)
void setup_Mc_kernel(const float* __restrict__ w_hh,
                     const float* __restrict__ dw2,
                     const float* __restrict__ db2)
{
    const int k = blockIdx.x;    // 0..191
    const int j = threadIdx.x;   // 0..63
    __shared__ float row[ND];
    row[j] = w_hh[k * ND + j];
    __syncthreads();
    float acc = 0.f;
#pragma unroll 8
    for (int i = 0; i < ND; i++) acc = fmaf(row[i], dw2[i * ND + j], acc);
    g_M[k * ND + j] = acc;
    if (j == 0) {
        float c = 0.f;
        for (int i = 0; i < ND; i++) c = fmaf(row[i], db2[i], c);
        g_c[k] = c;
    }
}

// ---------------- gx = x @ w_ih^T + b_ih (masked: t>=sl -> b_ih) -----------
__global__ __launch_bounds__(192)
void gx_kernel(const float* __restrict__ x,
               const int*   __restrict__ seq,
               const float* __restrict__ w_ih,
               const float* __restrict__ b_ih)
{
    const int b     = blockIdx.x;
    const int chunk = blockIdx.y;
    const int k     = threadIdx.x;          // 0..191 output row
    __shared__ __align__(16) float xs[GXR * ND];

    u64 w[32];
    const u64* wp = (const u64*)(w_ih + k * ND);
#pragma unroll
    for (int q = 0; q < 32; q++) w[q] = wp[q];
    const float bias = b_ih[k];

    const int t0 = chunk * GXR;
    const float4* src = (const float4*)(x + ((size_t)b * NL + t0) * ND);
    float4* dst = (float4*)xs;
    for (int i = k; i < GXR * ND / 4; i += 192) dst[i] = src[i];
    const int sl = seq[b];
    __syncthreads();

    float* og = g_gx + ((size_t)b * NL + t0) * NG + k;
#pragma unroll 4
    for (int r = 0; r < GXR; r++) {
        const int t = t0 + r;
        og[(size_t)r * NG] = (t < sl) ? dot64p(w, xs + r * ND, bias) : bias;
    }
}

// ---------------- recurrent kernel -----------------------------------------
__global__ __launch_bounds__(256, 1)
void odegru_kernel(const float* __restrict__ tdel,
                   const int*   __restrict__ seq,
                   const float* __restrict__ h0,
                   const float* __restrict__ w_hh,
                   const float* __restrict__ b_hh,
                   const float* __restrict__ dw1,
                   const float* __restrict__ db1,
                   const float* __restrict__ dw2,
                   const float* __restrict__ db2,
                   float* __restrict__ out)
{
    const int b   = blockIdx.x;
    const int tid = threadIdx.x;

    __shared__ __align__(16) float sh_h[ND];
    __shared__ __align__(16) float sh_t1[ND];
    __shared__ __align__(16) float sh_G1[NG];   // h*w_hh^T + b_hh
    __shared__ __align__(16) float sh_G2[NG];   // t1*M^T + c

    const int sl = seq[b];

    if (tid >= 192) {
        // ============ GATE WARPS (w6,w7 — highest priority) ============
        const int j = tid - 192;
        u64 wA[32], wB[32];                     // dw1 row j, dw2 row j
        {
            const u64* pA = (const u64*)(dw1 + j * ND);
            const u64* pB = (const u64*)(dw2 + j * ND);
#pragma unroll
            for (int k = 0; k < 32; k++) { wA[k] = pA[k]; wB[k] = pB[k]; }
        }
        const float bA = db1[j], bB = db2[j];
        const float* gxb = g_gx + (size_t)b * NL * NG;
        const float* dtb = tdel + (size_t)b * NL;
        float* outb = out + (size_t)b * NL * ND;

        float hreg = h0[j];
        sh_h[j] = hreg;
        float fin = 0.f;
        // gx/dt for t=0 (sl >= 1 so t=0 is live)
        float cg0 = gxb[j], cg1 = gxb[64 + j], cg2 = gxb[128 + j];
        float cdt = dtb[0];
        BARRIER();                              // pre: h visible

        for (int t = 0; t < NL; t++) {
            // A: issue prefetch for t+1 (consumed in C of t+1, ~5-phase
            // cover); t1 dot
            float ng0 = 0.f, ng1 = 0.f, ng2 = 0.f, ndt = 0.f;
            if (t + 1 < NL) {
                const float* g = gxb + (size_t)(t + 1) * NG;
                ng0 = g[j]; ng1 = g[64 + j]; ng2 = g[128 + j];
                ndt = (t + 1 < sl) ? dtb[t + 1] : 0.f;  // PaddedBatch mask
            }
            sh_t1[j] = tanh_ap(dot64p(wA, sh_h, bA));
            BARRIER();                          // syncA

            // B: f in register; preload G1 (final since syncA)
            float f    = dot64p(wB, sh_t1, bB);
            float G1_0 = sh_G1[j];
            float G1_1 = sh_G1[64 + j];
            float G1_2 = sh_G1[128 + j];
            BARRIER();                          // syncB

            // C: gates; gh = G1 + dt*G2; h and f never touch smem
            float ho = fmaf(cdt, f, hreg);
            float g0 = fmaf(cdt, sh_G2[j],       G1_0);
            float g1 = fmaf(cdt, sh_G2[64 + j],  G1_1);
            float g2 = fmaf(cdt, sh_G2[128 + j], G1_2);
            float r  = sigmoidf_(cg0 + g0);
            float z  = sigmoidf_(cg1 + g1);
            float n  = tanhf_fast(fmaf(r, g2, cg2));
            float hn = fmaf(z, ho - n, n);      // (1-z)*n + z*ho
            hreg = hn;
            sh_h[j] = hn;
            outb[(size_t)t * ND + j] = hn;
            if (t == sl - 1) fin = hn;
            cg0 = ng0; cg1 = ng1; cg2 = ng2; cdt = ndt;
            BARRIER();                          // syncC
        }
        // final hidden state -> second output tensor (1, B, D)
        out[(size_t)NB * NL * ND + (size_t)b * ND + j] = fin;
    } else {
        // ============ WORKER WARPS (w0-w5) ============
        const int k2 = tid;                     // 0..191
        u64 wA[32], wB[32];                     // w_hh row k2, M row k2
        {
            const u64* pA = (const u64*)(w_hh + k2 * ND);
            const u64* pB = (const u64*)(g_M + k2 * ND);
#pragma unroll
            for (int k = 0; k < 32; k++) { wA[k] = pA[k]; wB[k] = pB[k]; }
        }
        const float bA = b_hh[k2], bB = g_c[k2];
        BARRIER();                              // pre

        for (int t = 0; t < NL; t++) {
            sh_G1[k2] = dot64p(wA, sh_h, bA);   // A
            BARRIER();                          // syncA
            sh_G2[k2] = dot64p(wB, sh_t1, bB);  // B
            BARRIER();                          // syncB
            BARRIER();                          // syncC (idle in C)
        }
    }
}

extern "C" void kernel_launch(void* const* d_in, const int* in_sizes, int n_in,
                              void* d_out, int out_size)
{
    const float* x    = (const float*)d_in[0];
    const float* tdel = (const float*)d_in[1];
    const int*   seq  = (const int*)  d_in[2];
    const float* h0   = (const float*)d_in[3];
    const float* w_ih = (const float*)d_in[4];
    const float* w_hh = (const float*)d_in[5];
    const float* b_ih = (const float*)d_in[6];
    const float* b_hh = (const float*)d_in[7];
    const float* dw1  = (const float*)d_in[8];
    const float* db1  = (const float*)d_in[9];
    const float* dw2  = (const float*)d_in[10];
    const float* db2  = (const float*)d_in[11];

    setup_Mc_kernel<<<NG, 64>>>(w_hh, dw2, db2);
    dim3 ggrid(NB, NL / GXR);
    gx_kernel<<<ggrid, 192>>>(x, seq, w_ih, b_ih);
    odegru_kernel<<<NB, 256>>>(tdel, seq, h0, w_hh, b_hh,
                               dw1, db1, dw2, db2, (float*)d_out);
}